// round 2
// baseline (speedup 1.0000x reference)
#include <cuda_runtime.h>
#include <cstdint>

#define BB 32
#define TT 2048
#define CC 1152
#define OO 29
#define NCHUNK 16
#define TROWS (TT / NCHUNK)   // 128 t-rows per chunk
#define C4 (CC / 4)           // 288 float4 per row

// Scratch: per-(batch,chunk) partial column sums. Fully overwritten every
// launch by reduce_t_kernel before project_kernel reads it -> deterministic
// under graph replay, no zero-init needed, no device allocation.
__device__ float g_partial[BB * NCHUNK * CC];

// ---------------------------------------------------------------------------
// Kernel 1: stream x and reduce over the T dimension.
// grid = (BB * NCHUNK) blocks, 288 threads. Each thread owns one float4
// column-group and accumulates 128 rows (unroll 4 -> MLP >= 4 outstanding
// 16B loads per thread). Rows are 4608 B; 288 threads x 16 B covers a row
// exactly -> perfectly coalesced 128 B sectors.
// ---------------------------------------------------------------------------
__global__ __launch_bounds__(C4) void reduce_t_kernel(const float* __restrict__ x) {
    const int blk   = blockIdx.x;
    const int b     = blk / NCHUNK;
    const int chunk = blk % NCHUNK;
    const int c4    = threadIdx.x;

    const float4* xp = reinterpret_cast<const float4*>(x)
                     + ((size_t)b * TT + (size_t)chunk * TROWS) * C4 + c4;

    float4 acc = make_float4(0.f, 0.f, 0.f, 0.f);

    #pragma unroll 1
    for (int t = 0; t < TROWS; t += 4) {
        float4 v0 = xp[(size_t)(t + 0) * C4];
        float4 v1 = xp[(size_t)(t + 1) * C4];
        float4 v2 = xp[(size_t)(t + 2) * C4];
        float4 v3 = xp[(size_t)(t + 3) * C4];
        acc.x += (v0.x + v1.x) + (v2.x + v3.x);
        acc.y += (v0.y + v1.y) + (v2.y + v3.y);
        acc.z += (v0.z + v1.z) + (v2.z + v3.z);
        acc.w += (v0.w + v1.w) + (v2.w + v3.w);
    }

    reinterpret_cast<float4*>(g_partial)[(size_t)(b * NCHUNK + chunk) * C4 + c4] = acc;
}

// ---------------------------------------------------------------------------
// Kernel 2: collapse chunk partials, project onto W, add bias, divide by len.
// grid = BB blocks, 256 threads. Work per block is trivial (~70 KB reads).
// NOTE: length is int32 on device — JAX silently downcasts jnp.int64 to
// int32 when x64 mode is off (the default).
// ---------------------------------------------------------------------------
__global__ __launch_bounds__(256) void project_kernel(const int* __restrict__ length,
                                                      const float* __restrict__ W,
                                                      const float* __restrict__ bias,
                                                      float* __restrict__ out) {
    __shared__ float s[CC];
    const int b   = blockIdx.x;
    const int tid = threadIdx.x;

    // s[c] = sum over chunks of g_partial[b][chunk][c]
    for (int c = tid; c < CC; c += blockDim.x) {
        float v = 0.f;
        #pragma unroll
        for (int ch = 0; ch < NCHUNK; ch++)
            v += g_partial[(size_t)(b * NCHUNK + ch) * CC + c];
        s[c] = v;
    }
    __syncthreads();

    const int warp = tid >> 5;
    const int lane = tid & 31;
    const int nwarps = blockDim.x >> 5;   // 8
    const float inv_len = 1.0f / (float)length[b];

    for (int o = warp; o < OO; o += nwarps) {
        const float* wr = W + (size_t)o * CC;
        float dot = 0.f, wsum = 0.f;
        #pragma unroll
        for (int c = lane; c < CC; c += 32) {
            float w = wr[c];
            dot  = fmaf(s[c], w, dot);
            wsum += w;
        }
        #pragma unroll
        for (int off = 16; off; off >>= 1) {
            dot  += __shfl_down_sync(0xffffffffu, dot,  off);
            wsum += __shfl_down_sync(0xffffffffu, wsum, off);
        }
        if (lane == 0) {
            // z = dot/64 - 2*T*wsum + T*bias[o], then / length
            float z = dot * (1.0f / 64.0f)
                    - 2.0f * (float)TT * wsum
                    + (float)TT * bias[o];
            out[(size_t)b * OO + o] = z * inv_len;
        }
    }
}

// ---------------------------------------------------------------------------
// Inputs (metadata order): x f32 [B,T,C], length i32 [B], W f32 [O,C], b f32 [O]
// Output: f32 [B,O]
// ---------------------------------------------------------------------------
extern "C" void kernel_launch(void* const* d_in, const int* in_sizes, int n_in,
                              void* d_out, int out_size) {
    (void)in_sizes; (void)n_in; (void)out_size;
    const float* x      = (const float*)d_in[0];
    const int*   length = (const int*)d_in[1];
    const float* W      = (const float*)d_in[2];
    const float* bias   = (const float*)d_in[3];
    float*       out    = (float*)d_out;

    reduce_t_kernel<<<BB * NCHUNK, C4>>>(x);
    project_kernel<<<BB, 256>>>(length, W, bias, out);
}

// round 3
// speedup vs baseline: 1.0873x; 1.0873x over previous
#include <cuda_runtime.h>
#include <cstdint>

#define BB 32
#define TT 2048
#define CC 1152
#define OO 29
#define NCHUNK 16
#define TROWS (TT / NCHUNK)   // 128 t-rows per chunk
#define C4 (CC / 4)           // 288 float4 per row
#define ZP_STRIDE 32          // padded per-(b,chunk) output row

// Per-(b,chunk) projected partials: zp[b*NCHUNK+chunk][o].
// Fully overwritten by reduce_project_kernel every launch before the finish
// kernel reads it -> deterministic under graph replay, no zero-init needed.
__device__ float g_zp[BB * NCHUNK * ZP_STRIDE];

// ---------------------------------------------------------------------------
// Kernel 1: stream x, reduce over T within the chunk, then project the chunk's
// column-sum vector onto all 29 W rows in an smem epilogue.
//
//   zp[b,ch][o] = sum_c ( s_ch[c]/64 - 2*TROWS ) * W[o][c]
//
// grid = BB*NCHUNK = 512 blocks, 288 threads (one float4 column-group each,
// rows fully coalesced: 288 x 16B = 4608 B = one row). Mainloop unroll 4 ->
// MLP >= 4 outstanding 16B loads per thread; DRAM-bound at ~6.4 TB/s.
// W (133 KB) is L2-resident after the first wave, so the epilogue is
// L2-latency work fully overlapped with other blocks' DRAM streaming.
// ---------------------------------------------------------------------------
__global__ __launch_bounds__(C4) void reduce_project_kernel(const float* __restrict__ x,
                                                            const float* __restrict__ W) {
    __shared__ float s[CC];

    const int blk   = blockIdx.x;
    const int b     = blk / NCHUNK;
    const int chunk = blk % NCHUNK;
    const int c4    = threadIdx.x;

    const float4* xp = reinterpret_cast<const float4*>(x)
                     + ((size_t)b * TT + (size_t)chunk * TROWS) * C4 + c4;

    float4 acc = make_float4(0.f, 0.f, 0.f, 0.f);

    #pragma unroll 1
    for (int t = 0; t < TROWS; t += 4) {
        float4 v0 = xp[(size_t)(t + 0) * C4];
        float4 v1 = xp[(size_t)(t + 1) * C4];
        float4 v2 = xp[(size_t)(t + 2) * C4];
        float4 v3 = xp[(size_t)(t + 3) * C4];
        acc.x += (v0.x + v1.x) + (v2.x + v3.x);
        acc.y += (v0.y + v1.y) + (v2.y + v3.y);
        acc.z += (v0.z + v1.z) + (v2.z + v3.z);
        acc.w += (v0.w + v1.w) + (v2.w + v3.w);
    }

    reinterpret_cast<float4*>(s)[c4] = acc;
    __syncthreads();

    // Epilogue: 9 warps x (29 outputs round-robin). Fold the "-2 per element"
    // shift into the dot: val[c] = s[c]*(1/64) - 2*TROWS.
    const int warp  = c4 >> 5;          // 0..8
    const int lane  = c4 & 31;
    const float inv64 = 1.0f / 64.0f;
    const float shift = 2.0f * (float)TROWS;   // 256

    for (int o = warp; o < OO; o += 9) {
        const float* wr = W + (size_t)o * CC;
        float dot = 0.f;
        #pragma unroll
        for (int c = lane; c < CC; c += 32) {
            dot = fmaf(fmaf(s[c], inv64, -shift), wr[c], dot);
        }
        #pragma unroll
        for (int off = 16; off; off >>= 1)
            dot += __shfl_down_sync(0xffffffffu, dot, off);
        if (lane == 0)
            g_zp[(size_t)blk * ZP_STRIDE + o] = dot;
    }
}

// ---------------------------------------------------------------------------
// Kernel 2 (trivial): collapse 16 chunk partials, add T*bias, divide by len.
// grid = BB blocks, 32 threads; lanes read consecutive o -> coalesced.
// NOTE: length is int32 on device (JAX downcasts int64 with x64 off).
// ---------------------------------------------------------------------------
__global__ __launch_bounds__(32) void finish_kernel(const int* __restrict__ length,
                                                    const float* __restrict__ bias,
                                                    float* __restrict__ out) {
    const int b = blockIdx.x;
    const int o = threadIdx.x;
    if (o >= OO) return;

    float z = 0.f;
    #pragma unroll
    for (int ch = 0; ch < NCHUNK; ch++)
        z += g_zp[(size_t)(b * NCHUNK + ch) * ZP_STRIDE + o];

    z += (float)TT * bias[o];
    out[(size_t)b * OO + o] = z / (float)length[b];
}

// ---------------------------------------------------------------------------
// Inputs (metadata order): x f32 [B,T,C], length i32 [B], W f32 [O,C], b f32 [O]
// Output: f32 [B,O]
// ---------------------------------------------------------------------------
extern "C" void kernel_launch(void* const* d_in, const int* in_sizes, int n_in,
                              void* d_out, int out_size) {
    (void)in_sizes; (void)n_in; (void)out_size;
    const float* x      = (const float*)d_in[0];
    const int*   length = (const int*)d_in[1];
    const float* W      = (const float*)d_in[2];
    const float* bias   = (const float*)d_in[3];
    float*       out    = (float*)d_out;

    reduce_project_kernel<<<BB * NCHUNK, C4>>>(x, W);
    finish_kernel<<<BB, 32>>>(length, bias, out);
}

// round 4
// speedup vs baseline: 1.0917x; 1.0041x over previous
#include <cuda_runtime.h>
#include <cstdint>

#define BB 32
#define TT 2048
#define CC 1152
#define OO 29
#define NCHUNK 8
#define NBLK (BB * NCHUNK)    // 256 blocks
#define TROWS (TT / NCHUNK)   // 256 t-rows per chunk
#define C4 (CC / 4)           // 288 float4 per row
#define ZP_STRIDE 32          // padded per-(b,chunk) output row

// Per-(b,chunk) projected partials. Fully overwritten every launch before the
// finisher reads them -> deterministic under graph replay.
__device__ float    g_zp[NBLK * ZP_STRIDE];
// Block-completion counter; the finishing block resets it to 0 so every graph
// replay starts from the same state.
__device__ unsigned g_count;

// ---------------------------------------------------------------------------
// Single fused kernel:
//   (a) stream x, reduce TROWS rows over T within the chunk  (DRAM-bound)
//   (b) project the chunk column-sum vector onto all 29 W rows (L2-bound tail)
//   (c) last block to finish collapses chunk partials, adds T*bias, /length
//
// grid = 256 blocks x 288 threads; each thread owns one float4 column-group
// (288 x 16B = 4608 B = exactly one x row -> perfectly coalesced). Unroll 8
// -> >= 8 outstanding 16B loads/thread; 256 co-resident blocks give ~9.4 MB
// in flight vs the ~3.8 MB BW*latency product needed to saturate HBM.
// ---------------------------------------------------------------------------
__global__ __launch_bounds__(C4) void fused_kernel(const float* __restrict__ x,
                                                   const int*   __restrict__ length,
                                                   const float* __restrict__ W,
                                                   const float* __restrict__ bias,
                                                   float*       __restrict__ out) {
    __shared__ float s[CC];
    __shared__ bool  is_last;

    const int blk   = blockIdx.x;
    const int b     = blk / NCHUNK;
    const int chunk = blk % NCHUNK;
    const int tid   = threadIdx.x;

    // ---- (a) T-reduction mainloop ----
    const float4* xp = reinterpret_cast<const float4*>(x)
                     + ((size_t)b * TT + (size_t)chunk * TROWS) * C4 + tid;

    float4 acc = make_float4(0.f, 0.f, 0.f, 0.f);

    #pragma unroll 1
    for (int t = 0; t < TROWS; t += 8) {
        float4 v0 = xp[(size_t)(t + 0) * C4];
        float4 v1 = xp[(size_t)(t + 1) * C4];
        float4 v2 = xp[(size_t)(t + 2) * C4];
        float4 v3 = xp[(size_t)(t + 3) * C4];
        float4 v4 = xp[(size_t)(t + 4) * C4];
        float4 v5 = xp[(size_t)(t + 5) * C4];
        float4 v6 = xp[(size_t)(t + 6) * C4];
        float4 v7 = xp[(size_t)(t + 7) * C4];
        acc.x += ((v0.x + v1.x) + (v2.x + v3.x)) + ((v4.x + v5.x) + (v6.x + v7.x));
        acc.y += ((v0.y + v1.y) + (v2.y + v3.y)) + ((v4.y + v5.y) + (v6.y + v7.y));
        acc.z += ((v0.z + v1.z) + (v2.z + v3.z)) + ((v4.z + v5.z) + (v6.z + v7.z));
        acc.w += ((v0.w + v1.w) + (v2.w + v3.w)) + ((v4.w + v5.w) + (v6.w + v7.w));
    }

    reinterpret_cast<float4*>(s)[tid] = acc;
    __syncthreads();

    // ---- (b) projection epilogue: 9 warps round-robin the 29 outputs ----
    // val[c] = s[c]/64 - 2*TROWS, folded into the dot. float4 loads: 9 iters.
    const int warp = tid >> 5;
    const int lane = tid & 31;
    const float inv64 = 1.0f / 64.0f;
    const float shift = 2.0f * (float)TROWS;

    const float4* s4 = reinterpret_cast<const float4*>(s);

    for (int o = warp; o < OO; o += 9) {
        const float4* wr4 = reinterpret_cast<const float4*>(W + (size_t)o * CC);
        float dot = 0.f;
        #pragma unroll
        for (int k = 0; k < C4 / 32; k++) {          // 9 iterations
            int idx = lane + k * 32;
            float4 w = wr4[idx];
            float4 v = s4[idx];
            dot = fmaf(fmaf(v.x, inv64, -shift), w.x, dot);
            dot = fmaf(fmaf(v.y, inv64, -shift), w.y, dot);
            dot = fmaf(fmaf(v.z, inv64, -shift), w.z, dot);
            dot = fmaf(fmaf(v.w, inv64, -shift), w.w, dot);
        }
        #pragma unroll
        for (int off = 16; off; off >>= 1)
            dot += __shfl_down_sync(0xffffffffu, dot, off);
        if (lane == 0)
            g_zp[(size_t)blk * ZP_STRIDE + o] = dot;
    }

    // ---- (c) last-block finish ----
    __syncthreads();                    // all zp stores for this block issued
    if (tid == 0) {
        __threadfence();                // release: publish zp before counting
        unsigned old = atomicAdd(&g_count, 1u);
        is_last = (old == NBLK - 1);
    }
    __syncthreads();

    if (is_last) {
        __threadfence();                // acquire: see all blocks' zp
        for (int idx = tid; idx < BB * OO; idx += C4) {
            int bb = idx / OO;
            int oo = idx % OO;
            float z = 0.f;
            #pragma unroll
            for (int ch = 0; ch < NCHUNK; ch++)
                z += g_zp[(size_t)(bb * NCHUNK + ch) * ZP_STRIDE + oo];
            z += (float)TT * bias[oo];
            out[(size_t)bb * OO + oo] = z / (float)length[bb];
        }
        if (tid == 0) g_count = 0u;     // reset for next graph replay
    }
}

// ---------------------------------------------------------------------------
// Inputs (metadata order): x f32 [B,T,C], length i32 [B], W f32 [O,C], b f32 [O]
// Output: f32 [B,O]
// NOTE: length is int32 on device (JAX downcasts int64 with x64 off).
// ---------------------------------------------------------------------------
extern "C" void kernel_launch(void* const* d_in, const int* in_sizes, int n_in,
                              void* d_out, int out_size) {
    (void)in_sizes; (void)n_in; (void)out_size;
    const float* x      = (const float*)d_in[0];
    const int*   length = (const int*)d_in[1];
    const float* W      = (const float*)d_in[2];
    const float* bias   = (const float*)d_in[3];
    float*       out    = (float*)d_out;

    fused_kernel<<<NBLK, C4>>>(x, length, W, bias, out);
}